// round 11
// baseline (speedup 1.0000x reference)
#include <cuda_runtime.h>
#include <cuda_bf16.h>

#define BATCH 64
#define SEQT  512
#define HID   1024
#define G3    3072            // 3*H
#define MROWS 32768           // B*T
#define KP3   3072            // 3*K split-concat (big GEMM)
#define KP2   2048            // 2*K split (recurrent)

// ---------------- device scratch (no allocations allowed) ----------------
__device__ __nv_bfloat16 g_Abig[(size_t)MROWS * KP3];   // split activations (x / y0)
__device__ __nv_bfloat16 g_Wih0s[(size_t)G3 * KP3];
__device__ __nv_bfloat16 g_Wih1s[(size_t)G3 * KP3];
__device__ float         g_xg[(size_t)MROWS * G3];      // input-gate preactivations
__device__ float         g_y0[(size_t)MROWS * HID];     // layer0 outputs
__device__ float         g_hprev[2][BATCH * HID];
__device__ __nv_bfloat16 g_hs[2][BATCH * KP2];          // ping-pong split hidden
__device__ unsigned      g_barrier[2];                  // per-layer step barrier

// ---------------- helpers ----------------
__device__ __forceinline__ void mma_bf16(float c[4], const unsigned a[4], const unsigned b[2]) {
    asm volatile(
        "mma.sync.aligned.m16n8k16.row.col.f32.bf16.bf16.f32 "
        "{%0,%1,%2,%3}, {%4,%5,%6,%7}, {%8,%9}, {%0,%1,%2,%3};\n"
        : "+f"(c[0]), "+f"(c[1]), "+f"(c[2]), "+f"(c[3])
        : "r"(a[0]), "r"(a[1]), "r"(a[2]), "r"(a[3]), "r"(b[0]), "r"(b[1]));
}

// mode 0 (activations): out = [hi | hi | lo];  mode 1 (weights): out = [hi | lo | hi]
// dst_sel: 0 -> g_Abig, 1 -> g_Wih0s, 2 -> g_Wih1s.  use_y0: read g_y0 instead of src.
__global__ void split3_kernel(const float* __restrict__ src, int use_y0,
                              int dst_sel, int R, int C, int mode)
{
    __nv_bfloat16* out = (dst_sel == 0) ? g_Abig : (dst_sel == 1 ? g_Wih0s : g_Wih1s);
    const float* in = use_y0 ? g_y0 : src;
    int total = R * C;
    for (int i = blockIdx.x * blockDim.x + threadIdx.x; i < total;
         i += gridDim.x * blockDim.x) {
        int r = i / C;
        int c = i - r * C;
        float v = in[i];
        __nv_bfloat16 hi = __float2bfloat16(v);
        __nv_bfloat16 lo = __float2bfloat16(v - __bfloat162float(hi));
        __nv_bfloat16* o = out + (size_t)r * (3 * C);
        if (mode == 0) { o[c] = hi; o[C + c] = hi; o[2 * C + c] = lo; }
        else           { o[c] = hi; o[C + c] = lo; o[2 * C + c] = hi; }
    }
}

__global__ void hinit_kernel(const float* __restrict__ h0, int layer)
{
    if (blockIdx.x == 0 && threadIdx.x == 0) g_barrier[layer] = 0;
    int i = blockIdx.x * blockDim.x + threadIdx.x;
    if (i < BATCH * HID) {
        float v = h0[i];
        g_hprev[layer][i] = v;
        __nv_bfloat16 hi = __float2bfloat16(v);
        __nv_bfloat16 lo = __float2bfloat16(v - __bfloat162float(hi));
        int b = i >> 10, j = i & 1023;
        g_hs[0][b * KP2 + j] = hi;
        g_hs[0][b * KP2 + HID + j] = lo;
    }
}

__global__ void tail_kernel(float* __restrict__ out)
{
    int i = blockIdx.x * blockDim.x + threadIdx.x;
    if (i < 2 * BATCH * HID) {
        int layer = i / (BATCH * HID);
        int r = i - layer * (BATCH * HID);
        out[i] = g_hprev[layer][r];
    }
}

// ---------------- big GEMM: g_xg = g_Abig[M,Kp] * W'[N,Kp]^T + bias ----------------
#define GBM 128
#define GBN 128
#define GBK 32
#define GLD 40      // BK + 8 bf16 pad (conflict-free, 16B-aligned rows)

__global__ __launch_bounds__(256, 1) void gemm_big_kernel(int wsel, const float* __restrict__ bias)
{
    const __nv_bfloat16* A = g_Abig;
    const __nv_bfloat16* B = wsel ? g_Wih1s : g_Wih0s;
    float* C = g_xg;
    const int N = G3, Kp = KP3;

    __shared__ __nv_bfloat16 As[GBM * GLD];
    __shared__ __nv_bfloat16 Bs[GBN * GLD];

    int tid = threadIdx.x;
    int bn = blockIdx.x, bm = blockIdx.y;

    int s0 = tid, s1 = tid + 256;
    int ar0 = s0 >> 2, ac0 = (s0 & 3) << 3;
    int ar1 = s1 >> 2, ac1 = (s1 & 3) << 3;

    const __nv_bfloat16* Ag0 = A + (size_t)(bm * GBM + ar0) * Kp + ac0;
    const __nv_bfloat16* Ag1 = A + (size_t)(bm * GBM + ar1) * Kp + ac1;
    const __nv_bfloat16* Bg0 = B + (size_t)(bn * GBN + ar0) * Kp + ac0;
    const __nv_bfloat16* Bg1 = B + (size_t)(bn * GBN + ar1) * Kp + ac1;

    int warp = tid >> 5, lane = tid & 31;
    int wm = warp & 1, wn = warp >> 1;
    int gid = lane >> 2, tig = lane & 3;

    float acc[4][4][4];
    #pragma unroll
    for (int i = 0; i < 4; i++)
        #pragma unroll
        for (int j = 0; j < 4; j++)
            #pragma unroll
            for (int k = 0; k < 4; k++) acc[i][j][k] = 0.f;

    uint4 ra0 = *(const uint4*)Ag0;
    uint4 ra1 = *(const uint4*)Ag1;
    uint4 rb0 = *(const uint4*)Bg0;
    uint4 rb1 = *(const uint4*)Bg1;

    const int ksteps = Kp / GBK;
    for (int kt = 0; kt < ksteps; kt++) {
        *(uint4*)&As[ar0 * GLD + ac0] = ra0;
        *(uint4*)&As[ar1 * GLD + ac1] = ra1;
        *(uint4*)&Bs[ar0 * GLD + ac0] = rb0;
        *(uint4*)&Bs[ar1 * GLD + ac1] = rb1;
        __syncthreads();
        if (kt + 1 < ksteps) {
            int off = (kt + 1) * GBK;
            ra0 = *(const uint4*)(Ag0 + off);
            ra1 = *(const uint4*)(Ag1 + off);
            rb0 = *(const uint4*)(Bg0 + off);
            rb1 = *(const uint4*)(Bg1 + off);
        }
        #pragma unroll
        for (int kk = 0; kk < 2; kk++) {
            int kb = kk * 16 + 2 * tig;
            unsigned af[4][4], bf[4][2];
            #pragma unroll
            for (int mi = 0; mi < 4; mi++) {
                const __nv_bfloat16* p = &As[(wm * 64 + mi * 16 + gid) * GLD + kb];
                af[mi][0] = *(const unsigned*)p;
                af[mi][1] = *(const unsigned*)(p + 8 * GLD);
                af[mi][2] = *(const unsigned*)(p + 8);
                af[mi][3] = *(const unsigned*)(p + 8 * GLD + 8);
            }
            #pragma unroll
            for (int ni = 0; ni < 4; ni++) {
                const __nv_bfloat16* p = &Bs[(wn * 32 + ni * 8 + gid) * GLD + kb];
                bf[ni][0] = *(const unsigned*)p;
                bf[ni][1] = *(const unsigned*)(p + 8);
            }
            #pragma unroll
            for (int mi = 0; mi < 4; mi++)
                #pragma unroll
                for (int ni = 0; ni < 4; ni++)
                    mma_bf16(acc[mi][ni], af[mi], bf[ni]);
        }
        __syncthreads();
    }

    #pragma unroll
    for (int mi = 0; mi < 4; mi++) {
        int r0 = bm * GBM + wm * 64 + mi * 16 + gid;
        #pragma unroll
        for (int ni = 0; ni < 4; ni++) {
            int c0 = bn * GBN + wn * 32 + ni * 8 + 2 * tig;
            float bv0 = bias[c0], bv1 = bias[c0 + 1];
            float2 v0 = make_float2(acc[mi][ni][0] + bv0, acc[mi][ni][1] + bv1);
            float2 v1 = make_float2(acc[mi][ni][2] + bv0, acc[mi][ni][3] + bv1);
            *(float2*)&C[(size_t)r0 * N + c0] = v0;
            *(float2*)&C[(size_t)(r0 + 8) * N + c0] = v1;
        }
    }
}

// ---------------- persistent recurrent kernel (all 512 steps, one launch) ----------
// 128 blocks x 128 threads. Each block owns 8 hidden columns; W_hh rows for its
// 24 gate-columns live in shared memory for the whole layer. Steps separated by a
// device-wide monotonic-counter barrier (release/acquire).
#define SLD 72      // 64 + 8 pad
#define NBLK 128

__global__ __launch_bounds__(128, 1) void gru_persist_kernel(
    int layer, const float* __restrict__ w_hh, const float* __restrict__ bhh,
    float* __restrict__ yext, int use_ext)
{
    extern __shared__ __nv_bfloat16 sm[];
    __nv_bfloat16* sAh = sm;                         // 64*SLD = 4608
    __nv_bfloat16* sAl = sm + 64 * SLD;              // 4608
    __nv_bfloat16* sWh = sm + 2 * 64 * SLD;          // 16*24*SLD = 27648
    __nv_bfloat16* sWl = sWh + 16 * 24 * SLD;        // 27648

    float* hprev = g_hprev[layer];
    float* yout  = use_ext ? yext : g_y0;

    int tid = threadIdx.x;
    int j0 = blockIdx.x * 8;
    int warp = tid >> 5, lane = tid & 31;
    int gid = lane >> 2, tig = lane & 3;

    // ---- one-time: load + split this block's 24 W_hh rows into smem ----
    // local row r: gate = r>>3, col = j0 + (r&7); global W row = gate*HID + col.
    for (int idx = tid; idx < 24 * 256; idx += 128) {
        int r = idx >> 8;            // 0..23
        int q = idx & 255;           // 0..255 (q*4 floats within the 1024-row)
        int grow = (r >> 3) * HID + j0 + (r & 7);
        const float* src = w_hh + (size_t)grow * HID + q * 4;
        float4 v = *(const float4*)src;
        __nv_bfloat16 hi[4], lo[4];
        float vv[4] = {v.x, v.y, v.z, v.w};
        #pragma unroll
        for (int e = 0; e < 4; e++) {
            hi[e] = __float2bfloat16(vv[e]);
            lo[e] = __float2bfloat16(vv[e] - __bfloat162float(hi[e]));
        }
        int col = q * 4;             // 0..1020
        int kt = col >> 6;
        int c = col & 63;
        __nv_bfloat16* dh = sWh + kt * 24 * SLD + r * SLD + c;
        __nv_bfloat16* dl = sWl + kt * 24 * SLD + r * SLD + c;
        dh[0] = hi[0]; dh[1] = hi[1]; dh[2] = hi[2]; dh[3] = hi[3];
        dl[0] = lo[0]; dl[1] = lo[1]; dl[2] = lo[2]; dl[3] = lo[3];
    }
    __syncthreads();

    // A staging slots (64x64 chunk = 512 uint4 slots, 4 per thread)
    int as_r[4], as_c[4];
    #pragma unroll
    for (int i = 0; i < 4; i++) {
        int s = tid + i * 128;
        as_r[i] = s >> 3; as_c[i] = (s & 7) << 3;
    }

    unsigned* bar = &g_barrier[layer];

    for (int t = 0; t < SEQT; t++) {
        const __nv_bfloat16* Hs  = g_hs[t & 1];
        __nv_bfloat16*       Hso = g_hs[(t + 1) & 1];

        const __nv_bfloat16* Ar[4];
        #pragma unroll
        for (int i = 0; i < 4; i++)
            Ar[i] = Hs + (size_t)as_r[i] * KP2 + as_c[i];

        float acc[3][4];
        #pragma unroll
        for (int g = 0; g < 3; g++)
            #pragma unroll
            for (int k = 0; k < 4; k++) acc[g][k] = 0.f;

        uint4 pah[4], pal[4];
        #pragma unroll
        for (int i = 0; i < 4; i++) {
            pah[i] = *(const uint4*)(Ar[i]);
            pal[i] = *(const uint4*)(Ar[i] + HID);
        }

        const int ksteps = HID / 64;   // 16
        for (int kt = 0; kt < ksteps; kt++) {
            #pragma unroll
            for (int i = 0; i < 4; i++) {
                *(uint4*)&sAh[as_r[i] * SLD + as_c[i]] = pah[i];
                *(uint4*)&sAl[as_r[i] * SLD + as_c[i]] = pal[i];
            }
            __syncthreads();
            if (kt + 1 < ksteps) {
                int off = (kt + 1) * 64;
                #pragma unroll
                for (int i = 0; i < 4; i++) {
                    pah[i] = *(const uint4*)(Ar[i] + off);
                    pal[i] = *(const uint4*)(Ar[i] + HID + off);
                }
            }
            const __nv_bfloat16* wh = sWh + kt * 24 * SLD;
            const __nv_bfloat16* wl = sWl + kt * 24 * SLD;
            #pragma unroll
            for (int kk = 0; kk < 4; kk++) {
                int kb = kk * 16 + 2 * tig;
                unsigned ah[4], al[4];
                const __nv_bfloat16* p = &sAh[(warp * 16 + gid) * SLD + kb];
                ah[0] = *(const unsigned*)p;
                ah[1] = *(const unsigned*)(p + 8 * SLD);
                ah[2] = *(const unsigned*)(p + 8);
                ah[3] = *(const unsigned*)(p + 8 * SLD + 8);
                const __nv_bfloat16* q = &sAl[(warp * 16 + gid) * SLD + kb];
                al[0] = *(const unsigned*)q;
                al[1] = *(const unsigned*)(q + 8 * SLD);
                al[2] = *(const unsigned*)(q + 8);
                al[3] = *(const unsigned*)(q + 8 * SLD + 8);
                #pragma unroll
                for (int g = 0; g < 3; g++) {
                    unsigned bh[2], bl[2];
                    const __nv_bfloat16* r = &wh[(g * 8 + gid) * SLD + kb];
                    bh[0] = *(const unsigned*)r; bh[1] = *(const unsigned*)(r + 8);
                    const __nv_bfloat16* s = &wl[(g * 8 + gid) * SLD + kb];
                    bl[0] = *(const unsigned*)s; bl[1] = *(const unsigned*)(s + 8);
                    mma_bf16(acc[g], ah, bh);
                    mma_bf16(acc[g], ah, bl);
                    mma_bf16(acc[g], al, bh);
                }
            }
            __syncthreads();
        }

        // gates + state update (4 outputs per thread)
        #pragma unroll
        for (int ii = 0; ii < 4; ii++) {
            int b = warp * 16 + gid + ((ii >> 1) << 3);
            int j = j0 + 2 * tig + (ii & 1);
            const float* xgp = g_xg + ((size_t)b * SEQT + t) * G3;
            float r = 1.0f / (1.0f + expf(-(xgp[j] + acc[0][ii] + bhh[j])));
            float z = 1.0f / (1.0f + expf(-(xgp[HID + j] + acc[1][ii] + bhh[HID + j])));
            float n = tanhf(xgp[2 * HID + j] + r * (acc[2][ii] + bhh[2 * HID + j]));
            float hp = hprev[b * HID + j];
            float h = (1.0f - z) * n + z * hp;
            yout[((size_t)b * SEQT + t) * HID + j] = h;
            hprev[b * HID + j] = h;
            __nv_bfloat16 hi = __float2bfloat16(h);
            __nv_bfloat16 lo = __float2bfloat16(h - __bfloat162float(hi));
            Hso[b * KP2 + j] = hi;
            Hso[b * KP2 + HID + j] = lo;
        }

        // ---- device-wide step barrier (monotonic counter, release/acquire) ----
        __syncthreads();
        if (tid == 0) {
            unsigned tgt = (unsigned)(t + 1) * NBLK;
            asm volatile("red.release.gpu.global.add.u32 [%0], %1;"
                         :: "l"(bar), "r"(1u) : "memory");
            unsigned v;
            do {
                asm volatile("ld.acquire.gpu.global.u32 %0, [%1];"
                             : "=r"(v) : "l"(bar) : "memory");
            } while (v < tgt);
        }
        __syncthreads();
    }
}

// ---------------- launch ----------------
extern "C" void kernel_launch(void* const* d_in, const int* in_sizes, int n_in,
                              void* d_out, int out_size)
{
    const float* x      = (const float*)d_in[0];
    const float* hidden = (const float*)d_in[1];
    const float* w_ih0  = (const float*)d_in[2];
    const float* w_hh0  = (const float*)d_in[3];
    const float* b_ih0  = (const float*)d_in[4];
    const float* b_hh0  = (const float*)d_in[5];
    const float* w_ih1  = (const float*)d_in[6];
    const float* w_hh1  = (const float*)d_in[7];
    const float* b_ih1  = (const float*)d_in[8];
    const float* b_hh1  = (const float*)d_in[9];
    float* out = (float*)d_out;

    const int dyn_smem = (2 * 64 * SLD + 2 * 16 * 24 * SLD) * (int)sizeof(__nv_bfloat16); // 129024
    cudaFuncSetAttribute(gru_persist_kernel,
                         cudaFuncAttributeMaxDynamicSharedMemorySize, dyn_smem);

    // input-projection weight splits
    split3_kernel<<<1024, 256>>>(w_ih0, 0, 1, G3, HID, 1);
    split3_kernel<<<1024, 256>>>(w_ih1, 0, 2, G3, HID, 1);

    // ----- layer 0 -----
    split3_kernel<<<4096, 256>>>(x, 0, 0, MROWS, HID, 0);
    gemm_big_kernel<<<dim3(G3 / GBN, MROWS / GBM), 256>>>(0, b_ih0);
    hinit_kernel<<<256, 256>>>(hidden, 0);
    gru_persist_kernel<<<NBLK, 128, dyn_smem>>>(0, w_hh0, b_hh0, nullptr, 0);

    // ----- layer 1 -----
    split3_kernel<<<4096, 256>>>(nullptr, 1, 0, MROWS, HID, 0);
    gemm_big_kernel<<<dim3(G3 / GBN, MROWS / GBM), 256>>>(1, b_ih1);
    hinit_kernel<<<256, 256>>>(hidden + BATCH * HID, 1);
    gru_persist_kernel<<<NBLK, 128, dyn_smem>>>(1, w_hh1, b_hh1, out, 1);

    // final hidden states [2,B,H] appended after y1 (if the output carries them)
    if (out_size >= MROWS * HID + 2 * BATCH * HID)
        tail_kernel<<<512, 256>>>(out + (size_t)MROWS * HID);
}

// round 12
// speedup vs baseline: 1.6387x; 1.6387x over previous
#include <cuda_runtime.h>
#include <cuda_bf16.h>
#include <cstdint>

#define BATCH 64
#define SEQT  512
#define HID   1024
#define G3    3072            // 3*H
#define MROWS 32768           // B*T
#define KP3   3072            // 3*K split-concat (big GEMM)
#define KP2   2048            // 2*K split (recurrent)

// ---------------- device scratch (no allocations allowed) ----------------
__device__ __nv_bfloat16 g_Abig[(size_t)MROWS * KP3];   // split activations (x / y0)
__device__ __nv_bfloat16 g_Wih0s[(size_t)G3 * KP3];
__device__ __nv_bfloat16 g_Wih1s[(size_t)G3 * KP3];
__device__ float         g_xg[(size_t)MROWS * G3];      // input-gate preactivations
__device__ float         g_y0[(size_t)MROWS * HID];     // layer0 outputs
__device__ float         g_hprev[2][BATCH * HID];
__device__ __nv_bfloat16 g_hs[2][BATCH * KP2];          // ping-pong split hidden
__device__ unsigned      g_barrier[2];                  // per-layer step barrier

// ---------------- helpers ----------------
__device__ __forceinline__ void mma_bf16(float c[4], const unsigned a[4], const unsigned b[2]) {
    asm volatile(
        "mma.sync.aligned.m16n8k16.row.col.f32.bf16.bf16.f32 "
        "{%0,%1,%2,%3}, {%4,%5,%6,%7}, {%8,%9}, {%0,%1,%2,%3};\n"
        : "+f"(c[0]), "+f"(c[1]), "+f"(c[2]), "+f"(c[3])
        : "r"(a[0]), "r"(a[1]), "r"(a[2]), "r"(a[3]), "r"(b[0]), "r"(b[1]));
}

__device__ __forceinline__ void cp16(uint32_t saddr, const void* gptr) {
    asm volatile("cp.async.cg.shared.global [%0], [%1], 16;\n"
                 :: "r"(saddr), "l"(gptr));
}

// mode 0 (activations): out = [hi | hi | lo];  mode 1 (weights): out = [hi | lo | hi]
__global__ void split3_kernel(const float* __restrict__ src, int use_y0,
                              int dst_sel, int R, int C, int mode)
{
    __nv_bfloat16* out = (dst_sel == 0) ? g_Abig : (dst_sel == 1 ? g_Wih0s : g_Wih1s);
    const float* in = use_y0 ? g_y0 : src;
    int total = R * C;
    for (int i = blockIdx.x * blockDim.x + threadIdx.x; i < total;
         i += gridDim.x * blockDim.x) {
        int r = i / C;
        int c = i - r * C;
        float v = in[i];
        __nv_bfloat16 hi = __float2bfloat16(v);
        __nv_bfloat16 lo = __float2bfloat16(v - __bfloat162float(hi));
        __nv_bfloat16* o = out + (size_t)r * (3 * C);
        if (mode == 0) { o[c] = hi; o[C + c] = hi; o[2 * C + c] = lo; }
        else           { o[c] = hi; o[C + c] = lo; o[2 * C + c] = hi; }
    }
}

__global__ void hinit_kernel(const float* __restrict__ h0, int layer)
{
    if (blockIdx.x == 0 && threadIdx.x == 0) g_barrier[layer] = 0;
    int i = blockIdx.x * blockDim.x + threadIdx.x;
    if (i < BATCH * HID) {
        float v = h0[i];
        g_hprev[layer][i] = v;
        __nv_bfloat16 hi = __float2bfloat16(v);
        __nv_bfloat16 lo = __float2bfloat16(v - __bfloat162float(hi));
        int b = i >> 10, j = i & 1023;
        g_hs[0][b * KP2 + j] = hi;
        g_hs[0][b * KP2 + HID + j] = lo;
    }
}

__global__ void tail_kernel(float* __restrict__ out)
{
    int i = blockIdx.x * blockDim.x + threadIdx.x;
    if (i < 2 * BATCH * HID) {
        int layer = i / (BATCH * HID);
        int r = i - layer * (BATCH * HID);
        out[i] = g_hprev[layer][r];
    }
}

// ---------------- big GEMM: g_xg = g_Abig[M,Kp] * W'[N,Kp]^T + bias ----------------
#define GBM 128
#define GBN 128
#define GBK 32
#define GLD 40      // BK + 8 bf16 pad (conflict-free, 16B-aligned rows)
#define GSTAGES 3
#define GSTAGE_ELEMS ((GBM + GBN) * GLD)   // 10240 bf16 per stage

__global__ __launch_bounds__(256, 2) void gemm_big_kernel(int wsel, const float* __restrict__ bias)
{
    extern __shared__ __nv_bfloat16 gsm[];
    const __nv_bfloat16* A = g_Abig;
    const __nv_bfloat16* B = wsel ? g_Wih1s : g_Wih0s;
    float* C = g_xg;
    const int N = G3, Kp = KP3;

    int tid = threadIdx.x;
    int bn = blockIdx.x, bm = blockIdx.y;

    int s0 = tid, s1 = tid + 256;
    int ar0 = s0 >> 2, ac0 = (s0 & 3) << 3;
    int ar1 = s1 >> 2, ac1 = (s1 & 3) << 3;

    const __nv_bfloat16* Ag0 = A + (size_t)(bm * GBM + ar0) * Kp + ac0;
    const __nv_bfloat16* Ag1 = A + (size_t)(bm * GBM + ar1) * Kp + ac1;
    const __nv_bfloat16* Bg0 = B + (size_t)(bn * GBN + ar0) * Kp + ac0;
    const __nv_bfloat16* Bg1 = B + (size_t)(bn * GBN + ar1) * Kp + ac1;

    uint32_t sbase = (uint32_t)__cvta_generic_to_shared(gsm);
    uint32_t dA0 = (uint32_t)(ar0 * GLD + ac0) * 2;
    uint32_t dA1 = (uint32_t)(ar1 * GLD + ac1) * 2;
    uint32_t dB0 = (uint32_t)(GBM * GLD + ar0 * GLD + ac0) * 2;
    uint32_t dB1 = (uint32_t)(GBM * GLD + ar1 * GLD + ac1) * 2;

    int warp = tid >> 5, lane = tid & 31;
    int wm = warp & 1, wn = warp >> 1;
    int gid = lane >> 2, tig = lane & 3;

    float acc[4][4][4];
    #pragma unroll
    for (int i = 0; i < 4; i++)
        #pragma unroll
        for (int j = 0; j < 4; j++)
            #pragma unroll
            for (int k = 0; k < 4; k++) acc[i][j][k] = 0.f;

    const int ksteps = Kp / GBK;   // 96

    auto issue = [&](int kt) {
        uint32_t sb = sbase + (uint32_t)((kt % GSTAGES) * GSTAGE_ELEMS * 2);
        int off = kt * GBK;
        cp16(sb + dA0, Ag0 + off);
        cp16(sb + dA1, Ag1 + off);
        cp16(sb + dB0, Bg0 + off);
        cp16(sb + dB1, Bg1 + off);
        asm volatile("cp.async.commit_group;\n" ::: "memory");
    };

    issue(0);
    issue(1);

    for (int kt = 0; kt < ksteps; kt++) {
        if (kt + 1 < ksteps) asm volatile("cp.async.wait_group 1;\n" ::: "memory");
        else                 asm volatile("cp.async.wait_group 0;\n" ::: "memory");
        __syncthreads();
        if (kt + 2 < ksteps) issue(kt + 2);

        const __nv_bfloat16* As = gsm + (kt % GSTAGES) * GSTAGE_ELEMS;
        const __nv_bfloat16* Bs = As + GBM * GLD;

        #pragma unroll
        for (int kk = 0; kk < 2; kk++) {
            int kb = kk * 16 + 2 * tig;
            unsigned af[4][4], bf[4][2];
            #pragma unroll
            for (int mi = 0; mi < 4; mi++) {
                const __nv_bfloat16* p = &As[(wm * 64 + mi * 16 + gid) * GLD + kb];
                af[mi][0] = *(const unsigned*)p;
                af[mi][1] = *(const unsigned*)(p + 8 * GLD);
                af[mi][2] = *(const unsigned*)(p + 8);
                af[mi][3] = *(const unsigned*)(p + 8 * GLD + 8);
            }
            #pragma unroll
            for (int ni = 0; ni < 4; ni++) {
                const __nv_bfloat16* p = &Bs[(wn * 32 + ni * 8 + gid) * GLD + kb];
                bf[ni][0] = *(const unsigned*)p;
                bf[ni][1] = *(const unsigned*)(p + 8);
            }
            #pragma unroll
            for (int mi = 0; mi < 4; mi++)
                #pragma unroll
                for (int ni = 0; ni < 4; ni++)
                    mma_bf16(acc[mi][ni], af[mi], bf[ni]);
        }
        __syncthreads();
    }

    #pragma unroll
    for (int mi = 0; mi < 4; mi++) {
        int r0 = bm * GBM + wm * 64 + mi * 16 + gid;
        #pragma unroll
        for (int ni = 0; ni < 4; ni++) {
            int c0 = bn * GBN + wn * 32 + ni * 8 + 2 * tig;
            float bv0 = bias[c0], bv1 = bias[c0 + 1];
            float2 v0 = make_float2(acc[mi][ni][0] + bv0, acc[mi][ni][1] + bv1);
            float2 v1 = make_float2(acc[mi][ni][2] + bv0, acc[mi][ni][3] + bv1);
            *(float2*)&C[(size_t)r0 * N + c0] = v0;
            *(float2*)&C[(size_t)(r0 + 8) * N + c0] = v1;
        }
    }
}

// ---------------- persistent recurrent kernel (all 512 steps, one launch) ----------
// 128 blocks x 256 threads (two warp-groups split K). Each block owns 8 hidden
// columns; W_hh for its 24 gate-rows resident in shared memory. Device-wide
// monotonic-counter barrier separates steps.
#define SLD 72      // 64 + 8 pad
#define NBLK 128

__global__ __launch_bounds__(256, 1) void gru_persist_kernel(
    int layer, const float* __restrict__ w_hh, const float* __restrict__ bhh,
    float* __restrict__ yext, int use_ext)
{
    extern __shared__ __nv_bfloat16 sm[];
    // layout: [A0h 64*SLD][A0l][A1h][A1l][Wh 16*24*SLD][Wl 16*24*SLD]
    int tid = threadIdx.x;
    int group = tid >> 7;              // 0 or 1 (K halves)
    int gtid = tid & 127;
    int warp = tid >> 5;
    int wg = warp & 3;                 // warp within group
    int lane = tid & 31;
    int gid = lane >> 2, tig = lane & 3;
    int j0 = blockIdx.x * 8;

    __nv_bfloat16* sAh = sm + group * 2 * (64 * SLD);
    __nv_bfloat16* sAl = sAh + 64 * SLD;
    __nv_bfloat16* sWh = sm + 4 * (64 * SLD);
    __nv_bfloat16* sWl = sWh + 16 * 24 * SLD;
    float* redbuf = (float*)(sm + 2 * (64 * SLD));   // overlaps group-1 A staging

    float* hprev = g_hprev[layer];
    float* yout  = use_ext ? yext : g_y0;

    // ---- one-time: load + split this block's 24 W_hh rows into smem ----
    for (int idx = tid; idx < 24 * 256; idx += 256) {
        int r = idx >> 8;            // 0..23
        int q = idx & 255;
        int grow = (r >> 3) * HID + j0 + (r & 7);
        const float* src = w_hh + (size_t)grow * HID + q * 4;
        float4 v = *(const float4*)src;
        float vv[4] = {v.x, v.y, v.z, v.w};
        __nv_bfloat16 hi[4], lo[4];
        #pragma unroll
        for (int e = 0; e < 4; e++) {
            hi[e] = __float2bfloat16(vv[e]);
            lo[e] = __float2bfloat16(vv[e] - __bfloat162float(hi[e]));
        }
        int col = q * 4;
        int kt = col >> 6;
        int c = col & 63;
        __nv_bfloat16* dh = sWh + kt * 24 * SLD + r * SLD + c;
        __nv_bfloat16* dl = sWl + kt * 24 * SLD + r * SLD + c;
        dh[0] = hi[0]; dh[1] = hi[1]; dh[2] = hi[2]; dh[3] = hi[3];
        dl[0] = lo[0]; dl[1] = lo[1]; dl[2] = lo[2]; dl[3] = lo[3];
    }
    __syncthreads();

    // A staging slots: 64x64 chunk = 512 uint4 slots, 4 per (group-local) thread
    int as_r[4], as_c[4];
    #pragma unroll
    for (int i = 0; i < 4; i++) {
        int s = gtid + i * 128;
        as_r[i] = s >> 3; as_c[i] = (s & 7) << 3;
    }
    const int kbase = group * 512;     // this group's K offset
    const int ktg0 = group * 8;

    // per-thread persistent state (group 0 owns gates/outputs)
    int jj0 = j0 + 2 * tig;
    float hb[3][2];
    float hreg[4];
    if (group == 0) {
        #pragma unroll
        for (int g = 0; g < 3; g++) {
            hb[g][0] = bhh[g * HID + jj0];
            hb[g][1] = bhh[g * HID + jj0 + 1];
        }
        #pragma unroll
        for (int ii = 0; ii < 4; ii++) {
            int b = wg * 16 + gid + ((ii >> 1) << 3);
            int j = jj0 + (ii & 1);
            hreg[ii] = hprev[b * HID + j];
        }
    }

    unsigned* bar = &g_barrier[layer];
    int barid = group + 1;

    for (int t = 0; t < SEQT; t++) {
        const __nv_bfloat16* Hs  = g_hs[t & 1];
        __nv_bfloat16*       Hso = g_hs[(t + 1) & 1];

        const __nv_bfloat16* Ar[4];
        #pragma unroll
        for (int i = 0; i < 4; i++)
            Ar[i] = Hs + (size_t)as_r[i] * KP2 + kbase + as_c[i];

        // prefetch input-gate preactivations early (DRAM latency hidden by GEMM)
        float xr[3][4];
        if (group == 0) {
            #pragma unroll
            for (int ii = 0; ii < 4; ii++) {
                int b = wg * 16 + gid + ((ii >> 1) << 3);
                int j = jj0 + (ii & 1);
                const float* xgp = g_xg + ((size_t)b * SEQT + t) * G3 + j;
                xr[0][ii] = xgp[0];
                xr[1][ii] = xgp[HID];
                xr[2][ii] = xgp[2 * HID];
            }
        }

        float acc[3][4];
        #pragma unroll
        for (int g = 0; g < 3; g++)
            #pragma unroll
            for (int k = 0; k < 4; k++) acc[g][k] = 0.f;

        uint4 pah[4], pal[4];
        #pragma unroll
        for (int i = 0; i < 4; i++) {
            pah[i] = *(const uint4*)(Ar[i]);
            pal[i] = *(const uint4*)(Ar[i] + HID);
        }

        for (int kt = 0; kt < 8; kt++) {
            #pragma unroll
            for (int i = 0; i < 4; i++) {
                *(uint4*)&sAh[as_r[i] * SLD + as_c[i]] = pah[i];
                *(uint4*)&sAl[as_r[i] * SLD + as_c[i]] = pal[i];
            }
            asm volatile("bar.sync %0, %1;\n" :: "r"(barid), "r"(128) : "memory");
            if (kt < 7) {
                int off = (kt + 1) * 64;
                #pragma unroll
                for (int i = 0; i < 4; i++) {
                    pah[i] = *(const uint4*)(Ar[i] + off);
                    pal[i] = *(const uint4*)(Ar[i] + HID + off);
                }
            }
            const __nv_bfloat16* wh = sWh + (ktg0 + kt) * 24 * SLD;
            const __nv_bfloat16* wl = sWl + (ktg0 + kt) * 24 * SLD;
            #pragma unroll
            for (int kk = 0; kk < 4; kk++) {
                int kb = kk * 16 + 2 * tig;
                unsigned ah[4], al[4];
                const __nv_bfloat16* p = &sAh[(wg * 16 + gid) * SLD + kb];
                ah[0] = *(const unsigned*)p;
                ah[1] = *(const unsigned*)(p + 8 * SLD);
                ah[2] = *(const unsigned*)(p + 8);
                ah[3] = *(const unsigned*)(p + 8 * SLD + 8);
                const __nv_bfloat16* q = &sAl[(wg * 16 + gid) * SLD + kb];
                al[0] = *(const unsigned*)q;
                al[1] = *(const unsigned*)(q + 8 * SLD);
                al[2] = *(const unsigned*)(q + 8);
                al[3] = *(const unsigned*)(q + 8 * SLD + 8);
                #pragma unroll
                for (int g = 0; g < 3; g++) {
                    unsigned bh[2], bl[2];
                    const __nv_bfloat16* r = &wh[(g * 8 + gid) * SLD + kb];
                    bh[0] = *(const unsigned*)r; bh[1] = *(const unsigned*)(r + 8);
                    const __nv_bfloat16* s = &wl[(g * 8 + gid) * SLD + kb];
                    bl[0] = *(const unsigned*)s; bl[1] = *(const unsigned*)(s + 8);
                    mma_bf16(acc[g], ah, bh);
                    mma_bf16(acc[g], ah, bl);
                    mma_bf16(acc[g], al, bh);
                }
            }
            asm volatile("bar.sync %0, %1;\n" :: "r"(barid), "r"(128) : "memory");
        }

        // cross-group K reduction
        if (group == 1) {
            #pragma unroll
            for (int g = 0; g < 3; g++)
                #pragma unroll
                for (int ii = 0; ii < 4; ii++)
                    redbuf[gtid * 13 + g * 4 + ii] = acc[g][ii];
        }
        __syncthreads();

        if (group == 0) {
            #pragma unroll
            for (int g = 0; g < 3; g++)
                #pragma unroll
                for (int ii = 0; ii < 4; ii++)
                    acc[g][ii] += redbuf[gtid * 13 + g * 4 + ii];

            #pragma unroll
            for (int ii = 0; ii < 4; ii++) {
                int b = wg * 16 + gid + ((ii >> 1) << 3);
                int j = jj0 + (ii & 1);
                int e = ii & 1;
                float pr = xr[0][ii] + acc[0][ii] + hb[0][e];
                float pz = xr[1][ii] + acc[1][ii] + hb[1][e];
                float pn = xr[2][ii];
                float r = __fdividef(1.f, 1.f + __expf(-pr));
                float z = __fdividef(1.f, 1.f + __expf(-pz));
                float a = pn + r * (acc[2][ii] + hb[2][e]);
                float n = 1.f - __fdividef(2.f, __expf(2.f * a) + 1.f);
                float h = (1.f - z) * n + z * hreg[ii];
                hreg[ii] = h;
                yout[((size_t)b * SEQT + t) * HID + j] = h;
                if (t == SEQT - 1) hprev[b * HID + j] = h;
                __nv_bfloat16 hi = __float2bfloat16(h);
                __nv_bfloat16 lo = __float2bfloat16(h - __bfloat162float(hi));
                Hso[b * KP2 + j] = hi;
                Hso[b * KP2 + HID + j] = lo;
            }
        }
        __syncthreads();

        // ---- device-wide step barrier (monotonic counter, release/acquire) ----
        if (tid == 0) {
            unsigned tgt = (unsigned)(t + 1) * NBLK;
            asm volatile("red.release.gpu.global.add.u32 [%0], %1;"
                         :: "l"(bar), "r"(1u) : "memory");
            unsigned v;
            do {
                asm volatile("ld.acquire.gpu.global.u32 %0, [%1];"
                             : "=r"(v) : "l"(bar) : "memory");
            } while (v < tgt);
        }
        __syncthreads();
    }
}

// ---------------- launch ----------------
extern "C" void kernel_launch(void* const* d_in, const int* in_sizes, int n_in,
                              void* d_out, int out_size)
{
    const float* x      = (const float*)d_in[0];
    const float* hidden = (const float*)d_in[1];
    const float* w_ih0  = (const float*)d_in[2];
    const float* w_hh0  = (const float*)d_in[3];
    const float* b_ih0  = (const float*)d_in[4];
    const float* b_hh0  = (const float*)d_in[5];
    const float* w_ih1  = (const float*)d_in[6];
    const float* w_hh1  = (const float*)d_in[7];
    const float* b_ih1  = (const float*)d_in[8];
    const float* b_hh1  = (const float*)d_in[9];
    float* out = (float*)d_out;

    const int persist_smem = (4 * 64 * SLD + 2 * 16 * 24 * SLD) * (int)sizeof(__nv_bfloat16); // 147456
    cudaFuncSetAttribute(gru_persist_kernel,
                         cudaFuncAttributeMaxDynamicSharedMemorySize, persist_smem);
    const int gemm_smem = GSTAGES * GSTAGE_ELEMS * (int)sizeof(__nv_bfloat16);                // 61440
    cudaFuncSetAttribute(gemm_big_kernel,
                         cudaFuncAttributeMaxDynamicSharedMemorySize, gemm_smem);

    // input-projection weight splits
    split3_kernel<<<1024, 256>>>(w_ih0, 0, 1, G3, HID, 1);
    split3_kernel<<<1024, 256>>>(w_ih1, 0, 2, G3, HID, 1);

    // ----- layer 0 -----
    split3_kernel<<<4096, 256>>>(x, 0, 0, MROWS, HID, 0);
    gemm_big_kernel<<<dim3(G3 / GBN, MROWS / GBM), 256, gemm_smem>>>(0, b_ih0);
    hinit_kernel<<<256, 256>>>(hidden, 0);
    gru_persist_kernel<<<NBLK, 256, persist_smem>>>(0, w_hh0, b_hh0, nullptr, 0);

    // ----- layer 1 -----
    split3_kernel<<<4096, 256>>>(nullptr, 1, 0, MROWS, HID, 0);
    gemm_big_kernel<<<dim3(G3 / GBN, MROWS / GBM), 256, gemm_smem>>>(1, b_ih1);
    hinit_kernel<<<256, 256>>>(hidden + BATCH * HID, 1);
    gru_persist_kernel<<<NBLK, 256, persist_smem>>>(1, w_hh1, b_hh1, out, 1);

    // final hidden states [2,B,H] appended after y1 (if the output carries them)
    if (out_size >= MROWS * HID + 2 * BATCH * HID)
        tail_kernel<<<512, 256>>>(out + (size_t)MROWS * HID);
}